// round 2
// baseline (speedup 1.0000x reference)
#include <cuda_runtime.h>
#include <cuda_bf16.h>
#include <math.h>

// Problem constants
#define Bz   8
#define Cc   320
#define Dd   32
#define Hh   32
#define Ww   16
#define Ll   (Dd*Hh*Ww)        // 16384
#define Mtok (Bz*Ll)           // 131072
#define HEADS 10
#define HDIM  32
#define NWIN  512              // windows per sample
#define NTOK  32               // tokens per window

// Scratch (device globals; allocation-free kernel_launch)
__device__ float g_t   [(size_t)Mtok*Cc];     // residual stream (B,L,C)
__device__ float g_xn  [(size_t)Mtok*Cc];     // layernorm output
__device__ float g_qkv [(size_t)Mtok*960];    // qkv projections
__device__ float g_attn[(size_t)Mtok*Cc];     // attention output
__device__ float g_mlp [(size_t)Mtok*1280];   // mlp hidden

// ---------------------------------------------------------------------------
// Transpose (B,C,L) -> (B,L,C)
__global__ void transpose_cl_lc(const float* __restrict__ in, float* __restrict__ out) {
    __shared__ float tile[32][33];
    int b  = blockIdx.z;
    int l0 = blockIdx.x * 32, c0 = blockIdx.y * 32;
    int tx = threadIdx.x, ty = threadIdx.y;
    const float* src = in + (size_t)b * Cc * Ll;
    float* dst = out + (size_t)b * Ll * Cc;
    #pragma unroll
    for (int j = 0; j < 32; j += 8)
        tile[ty + j][tx] = src[(size_t)(c0 + ty + j) * Ll + l0 + tx];
    __syncthreads();
    #pragma unroll
    for (int j = 0; j < 32; j += 8)
        dst[(size_t)(l0 + ty + j) * Cc + c0 + tx] = tile[tx][ty + j];
}

// Transpose (B,L,C) -> (B,C,L)
__global__ void transpose_lc_cl(const float* __restrict__ in, float* __restrict__ out) {
    __shared__ float tile[32][33];
    int b  = blockIdx.z;
    int l0 = blockIdx.x * 32, c0 = blockIdx.y * 32;
    int tx = threadIdx.x, ty = threadIdx.y;
    const float* src = in + (size_t)b * Ll * Cc;
    float* dst = out + (size_t)b * Cc * Ll;
    #pragma unroll
    for (int j = 0; j < 32; j += 8)
        tile[ty + j][tx] = src[(size_t)(l0 + ty + j) * Cc + c0 + tx];
    __syncthreads();
    #pragma unroll
    for (int j = 0; j < 32; j += 8)
        dst[(size_t)(c0 + ty + j) * Ll + l0 + tx] = tile[tx][ty + j];
}

// ---------------------------------------------------------------------------
// LayerNorm over C=320 per token. 128 threads per row.
__global__ void ln_kernel(const float* __restrict__ x, const float* __restrict__ g,
                          const float* __restrict__ b, float* __restrict__ y) {
    __shared__ float red[8];
    int row = blockIdx.x;
    int tid = threadIdx.x;
    const float* xr = x + (size_t)row * Cc;
    float s = 0.f, s2 = 0.f;
    #pragma unroll
    for (int c = tid; c < Cc; c += 128) { float v = xr[c]; s += v; s2 += v * v; }
    #pragma unroll
    for (int o = 16; o > 0; o >>= 1) {
        s  += __shfl_down_sync(0xffffffffu, s,  o);
        s2 += __shfl_down_sync(0xffffffffu, s2, o);
    }
    if ((tid & 31) == 0) { red[tid >> 5] = s; red[4 + (tid >> 5)] = s2; }
    __syncthreads();
    if (tid == 0) {
        float a  = red[0] + red[1] + red[2] + red[3];
        float a2 = red[4] + red[5] + red[6] + red[7];
        red[0] = a * (1.f / Cc);
        red[4] = a2 * (1.f / Cc);
    }
    __syncthreads();
    float mu   = red[0];
    float var  = red[4] - mu * mu;
    float rstd = rsqrtf(var + 1e-5f);
    float* yr = y + (size_t)row * Cc;
    #pragma unroll
    for (int c = tid; c < Cc; c += 128)
        yr[c] = (xr[c] - mu) * rstd * g[c] + b[c];
}

// ---------------------------------------------------------------------------
// SGEMM: C_out = op(A @ B + bias). A: MxK row-major, B: KxN row-major.
// BM=128, BN=64, BK=16, 256 threads, TM=8, TN=4, double-buffered smem.
// MODE 0: store   MODE 1: accumulate into C (residual add)   MODE 2: GELU then store
template <int MODE>
__global__ void __launch_bounds__(256)
sgemm(const float* __restrict__ A, const float* __restrict__ B,
      const float* __restrict__ bias, float* __restrict__ C,
      int M, int N, int K) {
    const int BM = 128, BN = 64, BK = 16;
    const int TM = 8, TN = 4;
    __shared__ float As[2][BK][BM];   // k-major, transposed A tile
    __shared__ float Bs[2][BK][BN];

    int tid = threadIdx.x;
    int bm = blockIdx.y * BM, bn = blockIdx.x * BN;
    int tn = (tid % 16) * TN;         // 0..60
    int tm = (tid / 16) * TM;         // 0..120

    // A tile loads: 128x16 floats = 2 float4 / thread
    int a_r = tid >> 2;               // 0..63 (then +64)
    int a_c = (tid & 3) * 4;          // 0,4,8,12
    // B tile loads: 16x64 floats = 1 float4 / thread
    int b_r = tid >> 4;               // 0..15
    int b_c = (tid & 15) * 4;         // 0..60

    const float* Ap = A + (size_t)(bm + a_r) * K + a_c;
    const float* Bp = B + (size_t)b_r * N + bn + b_c;

    float acc[TM][TN];
    #pragma unroll
    for (int i = 0; i < TM; i++)
        #pragma unroll
        for (int j = 0; j < TN; j++) acc[i][j] = 0.f;

    float4 ra0, ra1, rb;

    // Prologue: load tile 0
    ra0 = *(const float4*)(Ap);
    ra1 = *(const float4*)(Ap + (size_t)64 * K);
    rb  = *(const float4*)(Bp);
    {
        As[0][a_c + 0][a_r]      = ra0.x;
        As[0][a_c + 1][a_r]      = ra0.y;
        As[0][a_c + 2][a_r]      = ra0.z;
        As[0][a_c + 3][a_r]      = ra0.w;
        As[0][a_c + 0][a_r + 64] = ra1.x;
        As[0][a_c + 1][a_r + 64] = ra1.y;
        As[0][a_c + 2][a_r + 64] = ra1.z;
        As[0][a_c + 3][a_r + 64] = ra1.w;
        *(float4*)&Bs[0][b_r][b_c] = rb;
    }
    __syncthreads();

    int ntiles = K / BK;
    int buf = 0;
    for (int it = 0; it < ntiles; it++) {
        if (it + 1 < ntiles) {
            int k0 = (it + 1) * BK;
            ra0 = *(const float4*)(Ap + k0);
            ra1 = *(const float4*)(Ap + (size_t)64 * K + k0);
            rb  = *(const float4*)(Bp + (size_t)k0 * N);
        }
        #pragma unroll
        for (int k = 0; k < BK; k++) {
            float4 a0 = *(const float4*)&As[buf][k][tm];
            float4 a1 = *(const float4*)&As[buf][k][tm + 4];
            float4 b0 = *(const float4*)&Bs[buf][k][tn];
            float ar[TM] = {a0.x, a0.y, a0.z, a0.w, a1.x, a1.y, a1.z, a1.w};
            float br[TN] = {b0.x, b0.y, b0.z, b0.w};
            #pragma unroll
            for (int i = 0; i < TM; i++)
                #pragma unroll
                for (int j = 0; j < TN; j++) acc[i][j] += ar[i] * br[j];
        }
        if (it + 1 < ntiles) {
            int nb = buf ^ 1;
            As[nb][a_c + 0][a_r]      = ra0.x;
            As[nb][a_c + 1][a_r]      = ra0.y;
            As[nb][a_c + 2][a_r]      = ra0.z;
            As[nb][a_c + 3][a_r]      = ra0.w;
            As[nb][a_c + 0][a_r + 64] = ra1.x;
            As[nb][a_c + 1][a_r + 64] = ra1.y;
            As[nb][a_c + 2][a_r + 64] = ra1.z;
            As[nb][a_c + 3][a_r + 64] = ra1.w;
            *(float4*)&Bs[nb][b_r][b_c] = rb;
            __syncthreads();
            buf = nb;
        }
    }

    #pragma unroll
    for (int j = 0; j < TN; j++) {
        float bb = bias[bn + tn + j];
        #pragma unroll
        for (int i = 0; i < TM; i++) {
            float r = acc[i][j] + bb;
            size_t idx = (size_t)(bm + tm + i) * N + bn + tn + j;
            if (MODE == 0) {
                C[idx] = r;
            } else if (MODE == 1) {
                C[idx] += r;
            } else {
                C[idx] = 0.5f * r * (1.f + erff(r * 0.70710678118654752440f));
            }
        }
    }
}

// ---------------------------------------------------------------------------
// Window attention. One block per window (320 threads = 10 warps = 10 heads).
// qkv layout per token row (960): [q|k|v], each head-major (head*32+d).
// Window partition / cyclic shift / reverse folded into index math; shift mask
// computed in closed form from region ids.
template <bool SHIFTED>
__global__ void __launch_bounds__(320)
attn_kernel(const float* __restrict__ qkv, const float* __restrict__ bias,
            float* __restrict__ out) {
    __shared__ float slab[HEADS * NTOK * 33];   // per-head 32x32 tile (padded)
    __shared__ float bsm[147 * HEADS];
    __shared__ int   l_idx[NTOK];
    __shared__ int   cnts[NTOK];

    int tid = threadIdx.x;
    int win = blockIdx.x;
    int b    = win / NWIN;
    int wrem = win % NWIN;
    int wd = wrem >> 6, wh = (wrem >> 3) & 7, ww = wrem & 7;

    for (int i = tid; i < 147 * HEADS; i += 320) bsm[i] = bias[i];

    if (tid < NTOK) {
        int id = tid >> 3, ih = (tid >> 1) & 3, iw = tid & 1;
        int d = wd * 4 + id, hh = wh * 4 + ih, wc = ww * 2 + iw;
        int sd = d, sh = hh, sw = wc;
        if (SHIFTED) { sd = (d + 2) & 31; sh = (hh + 2) & 31; sw = (wc + 1) & 15; }
        l_idx[tid] = ((b * Dd + sd) * Hh + sh) * Ww + sw;
        // region ids on shifted-frame coords
        int rd = (d  < 28) ? 0 : ((d  < 30) ? 1 : 2);
        int rh = (hh < 28) ? 0 : ((hh < 30) ? 1 : 2);
        int rw = (wc < 14) ? 0 : ((wc < 15) ? 1 : 2);
        cnts[tid] = rd * 9 + rh * 3 + rw;
    }
    __syncthreads();

    int h    = tid >> 5;
    int lane = tid & 31;
    float* sl = slab + h * NTOK * 33;

    // Load K tile: lane m holds row m of K
    {
        const float* kp = qkv + (size_t)l_idx[lane] * 960 + Cc + h * HDIM;
        #pragma unroll
        for (int d = 0; d < HDIM; d++) sl[lane * 33 + d] = kp[d];
    }
    __syncwarp();

    // q row for lane n, pre-scaled
    float qr[HDIM];
    {
        const float* qp = qkv + (size_t)l_idx[lane] * 960 + h * HDIM;
        #pragma unroll
        for (int d = 0; d < HDIM; d++) qr[d] = qp[d] * 0.17677669529663687f;
    }

    int id = lane >> 3, ih = (lane >> 1) & 3, iw = lane & 1;
    int my_cnt = cnts[lane];

    float p[NTOK];
    float mx = -1e30f;
    #pragma unroll
    for (int m = 0; m < NTOK; m++) {
        float s = 0.f;
        #pragma unroll
        for (int d = 0; d < HDIM; d++) s += qr[d] * sl[m * 33 + d];
        int md = m >> 3, mh = (m >> 1) & 3, mw = m & 1;
        int ridx = ((id - md + 3) * 7 + (ih - mh + 3)) * 3 + (iw - mw + 1);
        s += bsm[ridx * HEADS + h];
        if (SHIFTED && (my_cnt != cnts[m])) s -= 100.f;
        p[m] = s;
        mx = fmaxf(mx, s);
    }
    float sum = 0.f;
    #pragma unroll
    for (int m = 0; m < NTOK; m++) { p[m] = expf(p[m] - mx); sum += p[m]; }
    float inv = 1.f / sum;
    #pragma unroll
    for (int m = 0; m < NTOK; m++) p[m] *= inv;

    __syncwarp();
    // Load V tile over the same slab
    {
        const float* vp = qkv + (size_t)l_idx[lane] * 960 + 2 * Cc + h * HDIM;
        #pragma unroll
        for (int d = 0; d < HDIM; d++) sl[lane * 33 + d] = vp[d];
    }
    __syncwarp();

    float o[HDIM];
    #pragma unroll
    for (int d = 0; d < HDIM; d++) o[d] = 0.f;
    #pragma unroll
    for (int m = 0; m < NTOK; m++) {
        float pm = p[m];
        #pragma unroll
        for (int d = 0; d < HDIM; d++) o[d] += pm * sl[m * 33 + d];
    }

    float* op = out + (size_t)l_idx[lane] * Cc + h * HDIM;
    #pragma unroll
    for (int d = 0; d < HDIM; d++) op[d] = o[d];
}

// ---------------------------------------------------------------------------
static void run_block(bool shifted, float* t, float* xn, float* qkv, float* attn,
                      float* mlp, const float* const* p) {
    const int M = Mtok;
    ln_kernel<<<M, 128>>>(t, p[0], p[1], xn);
    sgemm<0><<<dim3(960 / 64, M / 128), 256>>>(xn, p[2], p[3], qkv, M, 960, Cc);
    if (shifted) attn_kernel<true ><<<Bz * NWIN, 320>>>(qkv, p[4], attn);
    else         attn_kernel<false><<<Bz * NWIN, 320>>>(qkv, p[4], attn);
    sgemm<1><<<dim3(320 / 64, M / 128), 256>>>(attn, p[5], p[6], t, M, 320, Cc);
    ln_kernel<<<M, 128>>>(t, p[7], p[8], xn);
    sgemm<2><<<dim3(1280 / 64, M / 128), 256>>>(xn, p[9], p[10], mlp, M, 1280, Cc);
    sgemm<1><<<dim3(320 / 64, M / 128), 256>>>(mlp, p[11], p[12], t, M, 320, 1280);
}

extern "C" void kernel_launch(void* const* d_in, const int* in_sizes, int n_in,
                              void* d_out, int out_size) {
    const float* x = (const float*)d_in[0];
    const float* p1[13];
    const float* p2[13];
    for (int i = 0; i < 13; i++) {
        p1[i] = (const float*)d_in[1 + i];
        p2[i] = (const float*)d_in[14 + i];
    }
    float *t, *xn, *qkv, *attn, *mlp;
    cudaGetSymbolAddress((void**)&t,    g_t);
    cudaGetSymbolAddress((void**)&xn,   g_xn);
    cudaGetSymbolAddress((void**)&qkv,  g_qkv);
    cudaGetSymbolAddress((void**)&attn, g_attn);
    cudaGetSymbolAddress((void**)&mlp,  g_mlp);

    dim3 tgrid(Ll / 32, Cc / 32, Bz), tblk(32, 8);
    transpose_cl_lc<<<tgrid, tblk>>>(x, t);
    run_block(false, t, xn, qkv, attn, mlp, p1);
    run_block(true,  t, xn, qkv, attn, mlp, p2);
    transpose_lc_cl<<<tgrid, tblk>>>(t, (float*)d_out);
}

// round 9
// speedup vs baseline: 3.9602x; 3.9602x over previous
#include <cuda_runtime.h>
#include <cuda_bf16.h>
#include <math.h>
#include <stdint.h>

// Problem constants
#define Bz   8
#define Cc   320
#define Dd   32
#define Hh   32
#define Ww   16
#define Ll   (Dd*Hh*Ww)        // 16384
#define Mtok (Bz*Ll)           // 131072
#define HEADS 10
#define HDIM  32
#define NWIN  512
#define NTOK  32

typedef __nv_bfloat16 bf16;

// Scratch (device globals)
__device__ float g_t    [(size_t)Mtok*Cc];      // residual stream fp32
__device__ bf16  g_xn   [(size_t)Mtok*Cc];      // LN output bf16
__device__ bf16  g_qkv  [(size_t)Mtok*960];     // qkv bf16
__device__ bf16  g_attn [(size_t)Mtok*Cc];      // attn out bf16
__device__ bf16  g_mlp  [(size_t)Mtok*1280];    // mlp hidden bf16
__device__ bf16  g_wq   [320*960];
__device__ bf16  g_wp   [320*320];
__device__ bf16  g_w1   [320*1280];
__device__ bf16  g_w2   [1280*320];

// ---------------------------------------------------------------------------
__device__ __forceinline__ uint32_t smem_u32(const void* p) {
    uint32_t a;
    asm("{ .reg .u64 t; cvta.to.shared.u64 t, %1; cvt.u32.u64 %0, t; }" : "=r"(a) : "l"(p));
    return a;
}
__device__ __forceinline__ void cp16(uint32_t s, const void* g) {
    asm volatile("cp.async.cg.shared.global [%0], [%1], 16;" :: "r"(s), "l"(g));
}
__device__ __forceinline__ void cp_commit() { asm volatile("cp.async.commit_group;"); }
__device__ __forceinline__ void cp_wait1()  { asm volatile("cp.async.wait_group 1;"); }
__device__ __forceinline__ void cp_wait0()  { asm volatile("cp.async.wait_group 0;"); }
__device__ __forceinline__ void ldsm4(uint32_t& r0, uint32_t& r1, uint32_t& r2, uint32_t& r3, uint32_t a) {
    asm volatile("ldmatrix.sync.aligned.m8n8.x4.shared.b16 {%0,%1,%2,%3}, [%4];"
                 : "=r"(r0), "=r"(r1), "=r"(r2), "=r"(r3) : "r"(a));
}
__device__ __forceinline__ void ldsm4t(uint32_t& r0, uint32_t& r1, uint32_t& r2, uint32_t& r3, uint32_t a) {
    asm volatile("ldmatrix.sync.aligned.m8n8.x4.trans.shared.b16 {%0,%1,%2,%3}, [%4];"
                 : "=r"(r0), "=r"(r1), "=r"(r2), "=r"(r3) : "r"(a));
}
__device__ __forceinline__ void mma16816(float* c, uint32_t a0, uint32_t a1, uint32_t a2, uint32_t a3,
                                         uint32_t b0, uint32_t b1) {
    asm volatile("mma.sync.aligned.m16n8k16.row.col.f32.bf16.bf16.f32 "
                 "{%0,%1,%2,%3}, {%4,%5,%6,%7}, {%8,%9}, {%0,%1,%2,%3};"
                 : "+f"(c[0]), "+f"(c[1]), "+f"(c[2]), "+f"(c[3])
                 : "r"(a0), "r"(a1), "r"(a2), "r"(a3), "r"(b0), "r"(b1));
}

// ---------------------------------------------------------------------------
__global__ void f2bf(const float* __restrict__ in, bf16* __restrict__ out, int n) {
    int i = blockIdx.x * blockDim.x + threadIdx.x;
    if (i < n) out[i] = __float2bfloat16(in[i]);
}

// Transpose (B,C,L) -> (B,L,C)
__global__ void transpose_cl_lc(const float* __restrict__ in, float* __restrict__ out) {
    __shared__ float tile[32][33];
    int b = blockIdx.z, l0 = blockIdx.x * 32, c0 = blockIdx.y * 32;
    int tx = threadIdx.x, ty = threadIdx.y;
    const float* src = in + (size_t)b * Cc * Ll;
    float* dst = out + (size_t)b * Ll * Cc;
    #pragma unroll
    for (int j = 0; j < 32; j += 8)
        tile[ty + j][tx] = src[(size_t)(c0 + ty + j) * Ll + l0 + tx];
    __syncthreads();
    #pragma unroll
    for (int j = 0; j < 32; j += 8)
        dst[(size_t)(l0 + ty + j) * Cc + c0 + tx] = tile[tx][ty + j];
}
__global__ void transpose_lc_cl(const float* __restrict__ in, float* __restrict__ out) {
    __shared__ float tile[32][33];
    int b = blockIdx.z, l0 = blockIdx.x * 32, c0 = blockIdx.y * 32;
    int tx = threadIdx.x, ty = threadIdx.y;
    const float* src = in + (size_t)b * Ll * Cc;
    float* dst = out + (size_t)b * Cc * Ll;
    #pragma unroll
    for (int j = 0; j < 32; j += 8)
        tile[ty + j][tx] = src[(size_t)(l0 + ty + j) * Cc + c0 + tx];
    __syncthreads();
    #pragma unroll
    for (int j = 0; j < 32; j += 8)
        dst[(size_t)(c0 + ty + j) * Ll + l0 + tx] = tile[tx][ty + j];
}

// ---------------------------------------------------------------------------
// LayerNorm: fp32 in -> bf16 out
__global__ void ln_kernel(const float* __restrict__ x, const float* __restrict__ g,
                          const float* __restrict__ b, bf16* __restrict__ y) {
    __shared__ float red[8];
    int row = blockIdx.x, tid = threadIdx.x;
    const float* xr = x + (size_t)row * Cc;
    float s = 0.f, s2 = 0.f;
    #pragma unroll
    for (int c = tid; c < Cc; c += 128) { float v = xr[c]; s += v; s2 += v * v; }
    #pragma unroll
    for (int o = 16; o > 0; o >>= 1) {
        s  += __shfl_down_sync(0xffffffffu, s,  o);
        s2 += __shfl_down_sync(0xffffffffu, s2, o);
    }
    if ((tid & 31) == 0) { red[tid >> 5] = s; red[4 + (tid >> 5)] = s2; }
    __syncthreads();
    if (tid == 0) {
        float a  = red[0] + red[1] + red[2] + red[3];
        float a2 = red[4] + red[5] + red[6] + red[7];
        red[0] = a * (1.f / Cc);
        red[4] = a2 * (1.f / Cc);
    }
    __syncthreads();
    float mu = red[0];
    float rstd = rsqrtf(red[4] - mu * mu + 1e-5f);
    bf16* yr = y + (size_t)row * Cc;
    #pragma unroll
    for (int c = tid; c < Cc; c += 128)
        yr[c] = __float2bfloat16((xr[c] - mu) * rstd * g[c] + b[c]);
}

// ---------------------------------------------------------------------------
// bf16 tensor-core GEMM: op(A[MxK] @ B[KxN] + bias)
// BM=128 BN=64 BK=32, 256 threads, cp.async double buffer, mma.m16n8k16.
// MODE 0: store bf16   MODE 1: accumulate into fp32 C   MODE 2: GELU -> bf16
template <int MODE>
__global__ void __launch_bounds__(256)
gemm_bf16(const bf16* __restrict__ A, const bf16* __restrict__ Bw,
          const float* __restrict__ bias, void* __restrict__ Cv,
          int M, int N, int K) {
    // padded strides: A rows 40 bf16 (80B), B rows 72 bf16 (144B)
    __shared__ __align__(16) bf16 As[2][128 * 40];
    __shared__ __align__(16) bf16 Bs[2][32 * 72];

    int tid = threadIdx.x;
    int bm = blockIdx.y * 128, bn = blockIdx.x * 64;
    int wid = tid >> 5, lane = tid & 31;
    int wm = (wid & 3) * 32, wn = (wid >> 2) * 32;
    int gq = lane >> 2, tq = lane & 3;

    uint32_t as_base = smem_u32(As);
    uint32_t bs_base = smem_u32(Bs);
    const uint32_t AS_STG = 128 * 40 * 2;  // bytes per stage
    const uint32_t BS_STG = 32 * 72 * 2;

    // A: 512 chunks of 16B, 2 per thread
    int ar = tid >> 2, ac = (tid & 3) * 8;
    const bf16* Ap0 = A + (size_t)(bm + ar) * K + ac;
    const bf16* Ap1 = Ap0 + (size_t)64 * K;
    uint32_t as_off0 = (uint32_t)(ar * 40 + ac) * 2;
    uint32_t as_off1 = (uint32_t)((ar + 64) * 40 + ac) * 2;
    // B: 256 chunks of 16B, 1 per thread
    int br = tid >> 3, bc = (tid & 7) * 8;
    const bf16* Bp = Bw + (size_t)br * N + bn + bc;
    uint32_t bs_off = (uint32_t)(br * 72 + bc) * 2;

    float acc[2][4][4];
    #pragma unroll
    for (int i = 0; i < 2; i++)
        #pragma unroll
        for (int j = 0; j < 4; j++)
            #pragma unroll
            for (int q = 0; q < 4; q++) acc[i][j][q] = 0.f;

    // prologue
    cp16(as_base + as_off0, Ap0);
    cp16(as_base + as_off1, Ap1);
    cp16(bs_base + bs_off, Bp);
    cp_commit();

    int nt = K / 32;
    for (int it = 0; it < nt; it++) {
        if (it + 1 < nt) {
            int k0 = (it + 1) * 32;
            uint32_t s = (uint32_t)((it + 1) & 1);
            cp16(as_base + s * AS_STG + as_off0, Ap0 + k0);
            cp16(as_base + s * AS_STG + as_off1, Ap1 + k0);
            cp16(bs_base + s * BS_STG + bs_off, Bp + (size_t)k0 * N);
            cp_commit();
            cp_wait1();
        } else {
            cp_wait0();
        }
        __syncthreads();

        uint32_t s = (uint32_t)(it & 1);
        uint32_t abase = as_base + s * AS_STG;
        uint32_t bbase = bs_base + s * BS_STG;
        #pragma unroll
        for (int ks = 0; ks < 32; ks += 16) {
            uint32_t a[2][4], b[2][4];
            #pragma unroll
            for (int mf = 0; mf < 2; mf++) {
                uint32_t addr = abase +
                    (uint32_t)((wm + mf * 16 + (lane & 15)) * 40 + ks + (lane >> 4) * 8) * 2;
                ldsm4(a[mf][0], a[mf][1], a[mf][2], a[mf][3], addr);
            }
            #pragma unroll
            for (int ng = 0; ng < 2; ng++) {
                uint32_t addr = bbase +
                    (uint32_t)((ks + (lane & 15)) * 72 + wn + ng * 16 + (lane >> 4) * 8) * 2;
                ldsm4t(b[ng][0], b[ng][1], b[ng][2], b[ng][3], addr);
            }
            #pragma unroll
            for (int mf = 0; mf < 2; mf++)
                #pragma unroll
                for (int ng = 0; ng < 2; ng++) {
                    mma16816(acc[mf][ng * 2 + 0], a[mf][0], a[mf][1], a[mf][2], a[mf][3],
                             b[ng][0], b[ng][1]);
                    mma16816(acc[mf][ng * 2 + 1], a[mf][0], a[mf][1], a[mf][2], a[mf][3],
                             b[ng][2], b[ng][3]);
                }
        }
        __syncthreads();
    }

    // epilogue
    #pragma unroll
    for (int mf = 0; mf < 2; mf++) {
        int r0 = bm + wm + mf * 16 + gq;
        #pragma unroll
        for (int j = 0; j < 4; j++) {
            int c = bn + wn + j * 8 + 2 * tq;
            float b0 = bias[c], b1 = bias[c + 1];
            float v00 = acc[mf][j][0] + b0, v01 = acc[mf][j][1] + b1;
            float v10 = acc[mf][j][2] + b0, v11 = acc[mf][j][3] + b1;
            if (MODE == 1) {
                float* C = (float*)Cv;
                size_t i0 = (size_t)r0 * N + c, i1 = (size_t)(r0 + 8) * N + c;
                C[i0] += v00; C[i0 + 1] += v01;
                C[i1] += v10; C[i1 + 1] += v11;
            } else {
                if (MODE == 2) {
                    v00 = 0.5f * v00 * (1.f + erff(v00 * 0.70710678118654752440f));
                    v01 = 0.5f * v01 * (1.f + erff(v01 * 0.70710678118654752440f));
                    v10 = 0.5f * v10 * (1.f + erff(v10 * 0.70710678118654752440f));
                    v11 = 0.5f * v11 * (1.f + erff(v11 * 0.70710678118654752440f));
                }
                bf16* C = (bf16*)Cv;
                *(__nv_bfloat162*)&C[(size_t)r0 * N + c]       = __floats2bfloat162_rn(v00, v01);
                *(__nv_bfloat162*)&C[(size_t)(r0 + 8) * N + c] = __floats2bfloat162_rn(v10, v11);
            }
        }
    }
}

// ---------------------------------------------------------------------------
// Window attention: bf16 qkv in, bf16 out; fp32 math; float4 slab (stride 36).
template <bool SHIFTED>
__global__ void __launch_bounds__(320)
attn_kernel(const bf16* __restrict__ qkv, const float* __restrict__ bias,
            bf16* __restrict__ out) {
    __shared__ __align__(16) float slab[HEADS * NTOK * 36];   // 46080 B
    __shared__ int l_idx[NTOK];
    __shared__ int cnts[NTOK];

    int tid = threadIdx.x;
    int win = blockIdx.x;
    int b = win / NWIN, wrem = win % NWIN;
    int wd = wrem >> 6, wh = (wrem >> 3) & 7, ww = wrem & 7;

    if (tid < NTOK) {
        int id = tid >> 3, ih = (tid >> 1) & 3, iw = tid & 1;
        int d = wd * 4 + id, hh = wh * 4 + ih, wc = ww * 2 + iw;
        int sd = d, sh = hh, sw = wc;
        if (SHIFTED) { sd = (d + 2) & 31; sh = (hh + 2) & 31; sw = (wc + 1) & 15; }
        l_idx[tid] = ((b * Dd + sd) * Hh + sh) * Ww + sw;
        int rd = (d  < 28) ? 0 : ((d  < 30) ? 1 : 2);
        int rh = (hh < 28) ? 0 : ((hh < 30) ? 1 : 2);
        int rw = (wc < 14) ? 0 : ((wc < 15) ? 1 : 2);
        cnts[tid] = rd * 9 + rh * 3 + rw;
    }
    __syncthreads();

    int h = tid >> 5, lane = tid & 31;
    float* sl = slab + h * (NTOK * 36);

    // K tile: lane m -> row m
    {
        const __nv_bfloat162* kp =
            (const __nv_bfloat162*)(qkv + (size_t)l_idx[lane] * 960 + Cc + h * HDIM);
        #pragma unroll
        for (int i = 0; i < 16; i++) {
            float2 f = __bfloat1622float2(kp[i]);
            sl[lane * 36 + 2 * i] = f.x;
            sl[lane * 36 + 2 * i + 1] = f.y;
        }
    }
    // q row, pre-scaled
    float4 qr[8];
    {
        const __nv_bfloat162* qp =
            (const __nv_bfloat162*)(qkv + (size_t)l_idx[lane] * 960 + h * HDIM);
        #pragma unroll
        for (int i = 0; i < 8; i++) {
            float2 f0 = __bfloat1622float2(qp[2 * i]);
            float2 f1 = __bfloat1622float2(qp[2 * i + 1]);
            qr[i] = make_float4(f0.x * 0.17677669529663687f, f0.y * 0.17677669529663687f,
                                f1.x * 0.17677669529663687f, f1.y * 0.17677669529663687f);
        }
    }
    __syncwarp();

    int id = lane >> 3, ih = (lane >> 1) & 3, iw = lane & 1;
    int my_cnt = cnts[lane];

    float p[NTOK];
    float mx = -1e30f;
    #pragma unroll
    for (int m = 0; m < NTOK; m++) {
        const float4* row = (const float4*)(sl + m * 36);
        float s = 0.f;
        #pragma unroll
        for (int i = 0; i < 8; i++) {
            float4 v = row[i];
            s += qr[i].x * v.x + qr[i].y * v.y + qr[i].z * v.z + qr[i].w * v.w;
        }
        int md = m >> 3, mh = (m >> 1) & 3, mw = m & 1;
        int ridx = ((id - md + 3) * 7 + (ih - mh + 3)) * 3 + (iw - mw + 1);
        s += __ldg(&bias[ridx * HEADS + h]);
        if (SHIFTED && (my_cnt != cnts[m])) s -= 100.f;
        p[m] = s;
        mx = fmaxf(mx, s);
    }
    float sum = 0.f;
    #pragma unroll
    for (int m = 0; m < NTOK; m++) { p[m] = expf(p[m] - mx); sum += p[m]; }
    float inv = 1.f / sum;

    __syncwarp();
    // V tile over the same slab
    {
        const __nv_bfloat162* vp =
            (const __nv_bfloat162*)(qkv + (size_t)l_idx[lane] * 960 + 2 * Cc + h * HDIM);
        #pragma unroll
        for (int i = 0; i < 16; i++) {
            float2 f = __bfloat1622float2(vp[i]);
            sl[lane * 36 + 2 * i] = f.x;
            sl[lane * 36 + 2 * i + 1] = f.y;
        }
    }
    __syncwarp();

    float4 o4[8];
    #pragma unroll
    for (int i = 0; i < 8; i++) o4[i] = make_float4(0.f, 0.f, 0.f, 0.f);
    #pragma unroll
    for (int m = 0; m < NTOK; m++) {
        float pm = p[m] * inv;
        const float4* row = (const float4*)(sl + m * 36);
        #pragma unroll
        for (int i = 0; i < 8; i++) {
            float4 v = row[i];
            o4[i].x += pm * v.x; o4[i].y += pm * v.y;
            o4[i].z += pm * v.z; o4[i].w += pm * v.w;
        }
    }

    __nv_bfloat162* op = (__nv_bfloat162*)(out + (size_t)l_idx[lane] * Cc + h * HDIM);
    #pragma unroll
    for (int i = 0; i < 8; i++) {
        op[2 * i]     = __floats2bfloat162_rn(o4[i].x, o4[i].y);
        op[2 * i + 1] = __floats2bfloat162_rn(o4[i].z, o4[i].w);
    }
}

// ---------------------------------------------------------------------------
static void run_block(bool shifted, float* t, bf16* xn, bf16* qkv, bf16* attn,
                      bf16* mlp, bf16* wq, bf16* wp, bf16* w1, bf16* w2,
                      const float* const* p) {
    const int M = Mtok;
    f2bf<<<(320*960 + 255) / 256, 256>>>(p[2],  wq, 320*960);
    f2bf<<<(320*320 + 255) / 256, 256>>>(p[5],  wp, 320*320);
    f2bf<<<(320*1280 + 255) / 256, 256>>>(p[9],  w1, 320*1280);
    f2bf<<<(1280*320 + 255) / 256, 256>>>(p[11], w2, 1280*320);

    ln_kernel<<<M, 128>>>(t, p[0], p[1], xn);
    gemm_bf16<0><<<dim3(960 / 64, M / 128), 256>>>(xn, wq, p[3], qkv, M, 960, Cc);
    if (shifted) attn_kernel<true ><<<Bz * NWIN, 320>>>(qkv, p[4], attn);
    else         attn_kernel<false><<<Bz * NWIN, 320>>>(qkv, p[4], attn);
    gemm_bf16<1><<<dim3(320 / 64, M / 128), 256>>>(attn, wp, p[6], t, M, 320, Cc);
    ln_kernel<<<M, 128>>>(t, p[7], p[8], xn);
    gemm_bf16<2><<<dim3(1280 / 64, M / 128), 256>>>(xn, w1, p[10], mlp, M, 1280, Cc);
    gemm_bf16<1><<<dim3(320 / 64, M / 128), 256>>>(mlp, w2, p[12], t, M, 320, 1280);
}

extern "C" void kernel_launch(void* const* d_in, const int* in_sizes, int n_in,
                              void* d_out, int out_size) {
    const float* x = (const float*)d_in[0];
    const float* p1[13];
    const float* p2[13];
    for (int i = 0; i < 13; i++) {
        p1[i] = (const float*)d_in[1 + i];
        p2[i] = (const float*)d_in[14 + i];
    }
    float* t;  bf16 *xn, *qkv, *attn, *mlp, *wq, *wp, *w1, *w2;
    cudaGetSymbolAddress((void**)&t,    g_t);
    cudaGetSymbolAddress((void**)&xn,   g_xn);
    cudaGetSymbolAddress((void**)&qkv,  g_qkv);
    cudaGetSymbolAddress((void**)&attn, g_attn);
    cudaGetSymbolAddress((void**)&mlp,  g_mlp);
    cudaGetSymbolAddress((void**)&wq,   g_wq);
    cudaGetSymbolAddress((void**)&wp,   g_wp);
    cudaGetSymbolAddress((void**)&w1,   g_w1);
    cudaGetSymbolAddress((void**)&w2,   g_w2);

    dim3 tgrid(Ll / 32, Cc / 32, Bz), tblk(32, 8);
    transpose_cl_lc<<<tgrid, tblk>>>(x, t);
    run_block(false, t, xn, qkv, attn, mlp, wq, wp, w1, w2, p1);
    run_block(true,  t, xn, qkv, attn, mlp, wq, wp, w1, w2, p2);
    transpose_lc_cl<<<tgrid, tblk>>>(t, (float*)d_out);
}